// round 14
// baseline (speedup 1.0000x reference)
#include <cuda_runtime.h>
#include <math.h>

#define BB 8
#define NN 1024
#define DIMM 256
#define DGG 128
#define SCALE 0.17677669529663687f   // 32^-0.5
#define LOG2E 1.4426950408889634f
#define RPE_SZ (63*63)               // 3969

typedef unsigned long long ull;
typedef unsigned int uint;

__device__ __forceinline__ uint f2tf(float f) {
    uint r; asm("cvt.rna.tf32.f32 %0, %1;" : "=r"(r) : "f"(f)); return r;
}

#define MMA_TF32(d, a, b) \
    asm("mma.sync.aligned.m16n8k8.row.col.f32.tf32.tf32.f32 " \
        "{%0,%1,%2,%3}, {%4,%5,%6,%7}, {%8,%9}, {%0,%1,%2,%3};" \
        : "+f"(d[0]), "+f"(d[1]), "+f"(d[2]), "+f"(d[3]) \
        : "r"(a[0]), "r"(a[1]), "r"(a[2]), "r"(a[3]), "r"(b[0]), "r"(b[1]))

// ---------------- scratch (static device globals; no allocs) ----------------
__device__ float g_q  [BB*NN*DIMM];      // q = x@Wq
__device__ float g_pos[BB*2*NN*2];       // sampling positions (y,x) per (bg,n)
__device__ float g_xs [BB*NN*DIMM];      // x_sampled
__device__ float g_kv [BB*NN*2*DIMM];    // kv = xs@Wkv
__device__ float g_att[BB*NN*DIMM];      // attention output (pre-Wout)

// ------ tf32 tensor-core GEMM, double-buffered: 128x128x16, 256 thr ---------
__global__ __launch_bounds__(256) void gemm_tf32(
    const float* __restrict__ A, const float* __restrict__ B,
    float* __restrict__ C, int M, int N, int K, const float* __restrict__ bias)
{
    __shared__ __align__(16) uint As[2][128][20];
    __shared__ __align__(16) uint Bs[2][16][136];
    const int tid  = threadIdx.x;
    const int lane = tid & 31, warp = tid >> 5;
    const int wm = (warp >> 1) * 32;
    const int wn = (warp & 1) * 64;
    const int gID = lane >> 2, tig = lane & 3;
    const int bm = blockIdx.y * 128, bn = blockIdx.x * 128;

    const int am  = tid >> 2, ak4 = (tid & 3) << 2;
    const int bkk = tid >> 5, bn4 = (tid & 31) << 2;

    float4 ra0, ra1, rb0, rb1;
    #define G_LD(k0) do { \
        ra0 = *(const float4*)&A[(size_t)(bm+am   )*K + (k0)+ak4]; \
        ra1 = *(const float4*)&A[(size_t)(bm+am+64)*K + (k0)+ak4]; \
        rb0 = *(const float4*)&B[(size_t)((k0)+bkk  )*N + bn+bn4]; \
        rb1 = *(const float4*)&B[(size_t)((k0)+bkk+8)*N + bn+bn4]; \
    } while(0)
    #define G_ST(bf) do { \
        uint4 t0 = {f2tf(ra0.x),f2tf(ra0.y),f2tf(ra0.z),f2tf(ra0.w)}; \
        uint4 t1 = {f2tf(ra1.x),f2tf(ra1.y),f2tf(ra1.z),f2tf(ra1.w)}; \
        uint4 t2 = {f2tf(rb0.x),f2tf(rb0.y),f2tf(rb0.z),f2tf(rb0.w)}; \
        uint4 t3 = {f2tf(rb1.x),f2tf(rb1.y),f2tf(rb1.z),f2tf(rb1.w)}; \
        *(uint4*)&As[bf][am   ][ak4] = t0; \
        *(uint4*)&As[bf][am+64][ak4] = t1; \
        *(uint4*)&Bs[bf][bkk  ][bn4] = t2; \
        *(uint4*)&Bs[bf][bkk+8][bn4] = t3; \
    } while(0)

    float c[2][8][4];
    #pragma unroll
    for (int rb=0;rb<2;rb++)
        #pragma unroll
        for (int nb=0;nb<8;nb++)
            #pragma unroll
            for (int r=0;r<4;r++) c[rb][nb][r]=0.f;

    G_LD(0); G_ST(0); __syncthreads();

    for (int k0 = 0; k0 < K; k0 += 16) {
        const int cur = (k0 >> 4) & 1;
        if (k0 + 16 < K) G_LD(k0 + 16);
        #pragma unroll
        for (int h8 = 0; h8 < 16; h8 += 8) {
            uint af[2][4];
            #pragma unroll
            for (int rb = 0; rb < 2; rb++) {
                int row = wm + rb*16;
                af[rb][0] = As[cur][row+gID  ][h8+tig  ];
                af[rb][1] = As[cur][row+gID+8][h8+tig  ];
                af[rb][2] = As[cur][row+gID  ][h8+tig+4];
                af[rb][3] = As[cur][row+gID+8][h8+tig+4];
            }
            uint bf[8][2];
            #pragma unroll
            for (int nb = 0; nb < 8; nb++) {
                int col = wn + nb*8 + gID;
                bf[nb][0] = Bs[cur][h8+tig  ][col];
                bf[nb][1] = Bs[cur][h8+tig+4][col];
            }
            #pragma unroll
            for (int rb = 0; rb < 2; rb++)
                #pragma unroll
                for (int nb = 0; nb < 8; nb++)
                    MMA_TF32(c[rb][nb], af[rb], bf[nb]);
        }
        if (k0 + 16 < K) { G_ST(cur^1); __syncthreads(); }
    }
    #pragma unroll
    for (int rb = 0; rb < 2; rb++) {
        int row0 = bm + wm + rb*16 + gID;
        #pragma unroll
        for (int nb = 0; nb < 8; nb++) {
            int col = bn + wn + nb*8 + tig*2;
            float b0 = 0.f, b1 = 0.f;
            if (bias) { float2 bv = *(const float2*)&bias[col]; b0 = bv.x; b1 = bv.y; }
            float2 o0 = {c[rb][nb][0] + b0, c[rb][nb][1] + b1};
            float2 o1 = {c[rb][nb][2] + b0, c[rb][nb][3] + b1};
            *(float2*)&C[(size_t)row0*N + col]     = o0;
            *(float2*)&C[(size_t)(row0+8)*N + col] = o1;
        }
    }
    #undef G_LD
    #undef G_ST
}

// -- conv 5x5 + LN + gelu + offset -> pos, FUSED with bilinear grid_sample ---
// grid 2048 (= 16 bg * 128 groups), 256 thr = 8 warps = 8 sites/block.
// lane owns 4 channels; after pos is reduced (all lanes have it via xor-shfl),
// each lane samples its own 4 channels at that pos -> xs. Barrier-free.
__global__ __launch_bounds__(256) void conv_sample_kernel(
    const float* __restrict__ q,
    const float* __restrict__ conv_w, const float* __restrict__ conv_b,
    const float* __restrict__ ln_g,   const float* __restrict__ ln_b,
    const float* __restrict__ Woff,   float* __restrict__ pos,
    float* __restrict__ xs)
{
    __shared__ float sw[25][128];    // transposed weights [tap][channel]
    const int tid = threadIdx.x;
    const int bg = blockIdx.x >> 7;
    const int b = bg >> 1, g = bg & 1;
    for (int idx = tid; idx < 25*128; idx += 256) {
        int cc = idx / 25, t = idx - cc*25;
        sw[t][cc] = conv_w[idx];
    }
    __syncthreads();

    const int warp = tid >> 5, lane = tid & 31;
    const int s = (blockIdx.x & 127)*8 + warp;   // site 0..1023
    const int y = s >> 5, x = s & 31;
    const int c4 = lane*4;

    float4 acc = *(const float4*)&conv_b[c4];
    const float* qbase = q + (size_t)b*NN*DIMM + g*DGG + c4;
    #pragma unroll
    for (int dy = 0; dy < 5; dy++) {
        int yy = y + dy - 2;
        if (yy < 0 || yy > 31) continue;
        #pragma unroll
        for (int dx = 0; dx < 5; dx++) {
            int xx = x + dx - 2;
            if (xx < 0 || xx > 31) continue;
            float4 qv = *(const float4*)&qbase[(size_t)(yy*32+xx)*DIMM];
            float4 wv = *(const float4*)&sw[dy*5+dx][c4];
            acc.x += qv.x*wv.x; acc.y += qv.y*wv.y;
            acc.z += qv.z*wv.z; acc.w += qv.w*wv.w;
        }
    }
    // LN over 128 channels
    float s1 = acc.x+acc.y+acc.z+acc.w;
    float s2 = acc.x*acc.x + acc.y*acc.y + acc.z*acc.z + acc.w*acc.w;
    #pragma unroll
    for (int o=16;o>0;o>>=1){ s1 += __shfl_xor_sync(0xffffffffu,s1,o);
                              s2 += __shfl_xor_sync(0xffffffffu,s2,o); }
    float mu  = s1 * (1.0f/128.0f);
    float var = s2 * (1.0f/128.0f) - mu*mu;
    float rstd = rsqrtf(var + 1e-5f);
    float4 lg4 = *(const float4*)&ln_g[c4];
    float4 lb4 = *(const float4*)&ln_b[c4];
    float v0 = (acc.x-mu)*rstd*lg4.x + lb4.x;
    float v1 = (acc.y-mu)*rstd*lg4.y + lb4.y;
    float v2 = (acc.z-mu)*rstd*lg4.z + lb4.z;
    float v3 = (acc.w-mu)*rstd*lg4.w + lb4.w;
    const float IS2 = 0.70710678118654752f;
    float ge0 = 0.5f*v0*(1.f+erff(v0*IS2));
    float ge1 = 0.5f*v1*(1.f+erff(v1*IS2));
    float ge2 = 0.5f*v2*(1.f+erff(v2*IS2));
    float ge3 = 0.5f*v3*(1.f+erff(v3*IS2));
    float4 wa = *(const float4*)&Woff[lane*8];
    float4 wb = *(const float4*)&Woff[lane*8+4];
    float o0 = ge0*wa.x + ge1*wa.z + ge2*wb.x + ge3*wb.z;
    float o1 = ge0*wa.y + ge1*wa.w + ge2*wb.y + ge3*wb.w;
    #pragma unroll
    for (int o=16;o>0;o>>=1){ o0 += __shfl_xor_sync(0xffffffffu,o0,o);
                              o1 += __shfl_xor_sync(0xffffffffu,o1,o); }
    // all lanes now hold the reductions
    float py = tanhf(o0)*0.0625f + ((2*y+1)*(1.0f/32.0f)-1.0f);
    float px = tanhf(o1)*0.0625f + ((2*x+1)*(1.0f/32.0f)-1.0f);
    if (lane == 0) {
        size_t idx = ((size_t)bg*NN + s)*2;
        pos[idx] = py; pos[idx+1] = px;
    }
    // ---- fused bilinear sample of this site's 4 channels ----
    const float pxs = (px + 1.f)*15.5f;
    const float pys = (py + 1.f)*15.5f;
    const float fx0 = floorf(pxs), fy0 = floorf(pys);
    float4 sacc = {0.f,0.f,0.f,0.f};
    #pragma unroll
    for (int dy=0; dy<2; dy++)
        #pragma unroll
        for (int dx=0; dx<2; dx++){
            float yi = fy0+dy, xi = fx0+dx;
            float wgt = (1.f - fabsf(pxs-xi))*(1.f - fabsf(pys-yi));
            bool valid = (yi>=0.f)&&(yi<32.f)&&(xi>=0.f)&&(xi<32.f);
            float w = valid ? wgt : 0.f;
            int yc = min(max((int)yi,0),31), xc = min(max((int)xi,0),31);
            float4 val = *(const float4*)&qbase[(size_t)(yc*32+xc)*DIMM];
            sacc.x += w*val.x; sacc.y += w*val.y; sacc.z += w*val.z; sacc.w += w*val.w;
        }
    *(float4*)&xs[((size_t)b*NN+s)*DIMM + g*DGG + c4] = sacc;
}

// ------------- tensor-core flash attention, double-buffered -----------------
// Block = (b, h, i-tile 64), 4 warps of 16 query rows; j-tile 32.
// log2-domain softmax (q and rpe pre-scaled by log2e; exp2 only).
// Weight guards dropped: pxr,pyr proven within [-0.01, 62.01]; border taps
// carry weight <= 0.01 so clamped-index contamination is negligible.
__global__ __launch_bounds__(128) void attn_mma(
    const float* __restrict__ q, const float* __restrict__ kv,
    const float* __restrict__ pos, const float* __restrict__ rpe,
    float* __restrict__ out)
{
    __shared__ __align__(16) uint sK[2][32][36];
    __shared__ __align__(16) uint sV[2][32][40];
    __shared__ __align__(16) uint sP[64][36];
    __shared__ float srpe[RPE_SZ];
    __shared__ float sPos[2][64];   // [0..32)=15.5*py, [32..64)=15.5*px

    const int it = blockIdx.x, h = blockIdx.y, b = blockIdx.z;
    const int bg = b*2 + (h>>2);
    const int tid = threadIdx.x;
    const int warp = tid>>5, lane = tid&31;
    const int gID = lane>>2, tig = lane&3;
    const int rb = warp*16;
    const int i0 = it*64 + rb + gID, i1 = i0 + 8;

    for (int t = tid; t < RPE_SZ; t += 128) srpe[t] = rpe[h*RPE_SZ + t] * LOG2E;

    const int lrow = tid >> 2, lq4 = (tid & 3) * 8;
    float4 rk0, rk1, rv0, rv1; float2 rpos;
    #define A_LD(jt) do { \
        const float* kp = &kv[((size_t)b*NN + (jt)*32 + lrow)*512 + h*32 + lq4]; \
        rk0 = *(const float4*)kp;       rk1 = *(const float4*)(kp+4); \
        rv0 = *(const float4*)(kp+256); rv1 = *(const float4*)(kp+260); \
        if (tid < 32) rpos = *(const float2*)&pos[((size_t)bg*NN + (jt)*32 + tid)*2]; \
    } while(0)
    #define A_ST(bf) do { \
        uint4 t0 = {f2tf(rk0.x),f2tf(rk0.y),f2tf(rk0.z),f2tf(rk0.w)}; \
        uint4 t1 = {f2tf(rk1.x),f2tf(rk1.y),f2tf(rk1.z),f2tf(rk1.w)}; \
        uint4 t2 = {f2tf(rv0.x),f2tf(rv0.y),f2tf(rv0.z),f2tf(rv0.w)}; \
        uint4 t3 = {f2tf(rv1.x),f2tf(rv1.y),f2tf(rv1.z),f2tf(rv1.w)}; \
        *(uint4*)&sK[bf][lrow][lq4  ] = t0; \
        *(uint4*)&sK[bf][lrow][lq4+4] = t1; \
        *(uint4*)&sV[bf][lrow][lq4  ] = t2; \
        *(uint4*)&sV[bf][lrow][lq4+4] = t3; \
        if (tid < 32) { sPos[bf][tid] = 15.5f*rpos.x; sPos[bf][32+tid] = 15.5f*rpos.y; } \
    } while(0)

    // Q fragments pre-scaled by SCALE*log2e
    uint qa[4][4];
    {
        const float QS = SCALE * LOG2E;
        const float* q0 = q + ((size_t)b*NN + i0)*DIMM + h*32;
        const float* q1 = q + ((size_t)b*NN + i1)*DIMM + h*32;
        #pragma unroll
        for (int k = 0; k < 4; k++) {
            qa[k][0] = f2tf(q0[k*8+tig  ]*QS);
            qa[k][1] = f2tf(q1[k*8+tig  ]*QS);
            qa[k][2] = f2tf(q0[k*8+tig+4]*QS);
            qa[k][3] = f2tf(q1[k*8+tig+4]*QS);
        }
    }
    const float cy  = 15.5f*((2*(i0>>5)+1)*(1.0f/32.0f)-1.0f) + 31.f;
    const float cx0 = 15.5f*((2*(i0&31)+1)*(1.0f/32.0f)-1.0f) + 31.f;
    const float cx1 = 15.5f*((2*(i1&31)+1)*(1.0f/32.0f)-1.0f) + 31.f;

    float dacc[4][4];
    #pragma unroll
    for (int nt=0;nt<4;nt++)
        #pragma unroll
        for (int r=0;r<4;r++) dacc[nt][r]=0.f;
    float l0 = 0.f, l1 = 0.f;

    A_LD(0); A_ST(0); __syncthreads();

    #pragma unroll 1
    for (int jt = 0; jt < 32; jt++) {
        const int cur = jt & 1;
        if (jt + 1 < 32) A_LD(jt + 1);

        // ---- S = Qs K^T (log2 domain) ----
        float c[4][4];
        #pragma unroll
        for (int nt=0;nt<4;nt++)
            #pragma unroll
            for (int r=0;r<4;r++) c[nt][r]=0.f;
        #pragma unroll
        for (int nt = 0; nt < 4; nt++) {
            #pragma unroll
            for (int k = 0; k < 4; k++) {
                uint bf[2] = { sK[cur][nt*8+gID][k*8+tig], sK[cur][nt*8+gID][k*8+tig+4] };
                MMA_TF32(c[nt], qa[k], bf);
            }
        }

        // ---- bias + exp2 -> tf32 P frags (y-part shared across both rows) --
        uint pf[4][4];
        #pragma unroll
        for (int nt = 0; nt < 4; nt++) {
            #pragma unroll
            for (int cp = 0; cp < 2; cp++) {
                int jl = nt*8 + 2*tig + cp;
                float py = sPos[cur][jl], px = sPos[cur][32+jl];
                float pyr = cy - py;
                float fy = floorf(pyr); int y0 = (int)fy;
                float wy1 = pyr - fy, wy0 = 1.f - wy1;
                int yc0 = max(y0,0), yc1 = min(y0+1,62);
                const float* r0 = &srpe[yc0*63];
                const float* r1 = &srpe[yc1*63];
                {
                    float pxr = cx0 - px;
                    float fx = floorf(pxr); int x0 = (int)fx;
                    float wx1 = pxr - fx, wx0 = 1.f - wx1;
                    int xc0 = max(x0,0), xc1 = min(x0+1,62);
                    float bias = wy0*(wx0*r0[xc0] + wx1*r0[xc1])
                               + wy1*(wx0*r1[xc0] + wx1*r1[xc1]);
                    uint pu = f2tf(exp2f(c[nt][cp] + bias));
                    l0 += __uint_as_float(pu);
                    pf[nt][cp] = pu;
                }
                {
                    float pxr = cx1 - px;
                    float fx = floorf(pxr); int x0 = (int)fx;
                    float wx1 = pxr - fx, wx0 = 1.f - wx1;
                    int xc0 = max(x0,0), xc1 = min(x0+1,62);
                    float bias = wy0*(wx0*r0[xc0] + wx1*r0[xc1])
                               + wy1*(wx0*r1[xc0] + wx1*r1[xc1]);
                    uint pu = f2tf(exp2f(c[nt][cp+2] + bias));
                    l1 += __uint_as_float(pu);
                    pf[nt][cp+2] = pu;
                }
            }
        }

        // ---- P -> per-warp smem rows ----
        #pragma unroll
        for (int nt = 0; nt < 4; nt++) {
            *(uint2*)&sP[rb+gID  ][nt*8+2*tig] = make_uint2(pf[nt][0], pf[nt][1]);
            *(uint2*)&sP[rb+gID+8][nt*8+2*tig] = make_uint2(pf[nt][2], pf[nt][3]);
        }
        __syncwarp();

        // ---- O += P V ----
        #pragma unroll
        for (int k = 0; k < 4; k++) {
            uint a[4] = { sP[rb+gID  ][k*8+tig  ], sP[rb+gID+8][k*8+tig  ],
                          sP[rb+gID  ][k*8+tig+4], sP[rb+gID+8][k*8+tig+4] };
            #pragma unroll
            for (int nt = 0; nt < 4; nt++) {
                uint bf[2] = { sV[cur][k*8+tig][nt*8+gID], sV[cur][k*8+tig+4][nt*8+gID] };
                MMA_TF32(dacc[nt], a, bf);
            }
        }
        __syncwarp();

        if (jt + 1 < 32) { A_ST(cur^1); __syncthreads(); }
    }

    l0 += __shfl_xor_sync(0xffffffffu, l0, 1);
    l0 += __shfl_xor_sync(0xffffffffu, l0, 2);
    l1 += __shfl_xor_sync(0xffffffffu, l1, 1);
    l1 += __shfl_xor_sync(0xffffffffu, l1, 2);
    float inv0 = 1.f/l0, inv1 = 1.f/l1;
    float* o0 = out + ((size_t)b*NN + i0)*DIMM + h*32;
    float* o1 = out + ((size_t)b*NN + i1)*DIMM + h*32;
    #pragma unroll
    for (int nt = 0; nt < 4; nt++) {
        *(float2*)&o0[nt*8+2*tig] = make_float2(dacc[nt][0]*inv0, dacc[nt][1]*inv0);
        *(float2*)&o1[nt*8+2*tig] = make_float2(dacc[nt][2]*inv1, dacc[nt][3]*inv1);
    }
    #undef A_LD
    #undef A_ST
}

// ---------------------------------------------------------------------------
extern "C" void kernel_launch(void* const* d_in, const int* in_sizes, int n_in,
                              void* d_out, int out_size)
{
    const float* x      = (const float*)d_in[0];
    const float* Wq     = (const float*)d_in[1];
    const float* Wkv    = (const float*)d_in[2];
    const float* conv_w = (const float*)d_in[3];
    const float* conv_b = (const float*)d_in[4];
    const float* ln_g   = (const float*)d_in[5];
    const float* ln_b   = (const float*)d_in[6];
    const float* Woff   = (const float*)d_in[7];
    const float* rpe    = (const float*)d_in[8];
    const float* Wout   = (const float*)d_in[9];
    const float* bout   = (const float*)d_in[10];
    float* outp = (float*)d_out;

    float *pq, *ppos, *pxs, *pkv, *patt;
    cudaGetSymbolAddress((void**)&pq,   g_q);
    cudaGetSymbolAddress((void**)&ppos, g_pos);
    cudaGetSymbolAddress((void**)&pxs,  g_xs);
    cudaGetSymbolAddress((void**)&pkv,  g_kv);
    cudaGetSymbolAddress((void**)&patt, g_att);

    // 1. q = x @ Wq
    gemm_tf32<<<dim3(2,64), 256>>>(x, Wq, pq, 8192, 256, 256, nullptr);
    // 2. conv+LN+gelu+offset -> pos, fused with grid_sample -> xs
    conv_sample_kernel<<<2048, 256>>>(pq, conv_w, conv_b, ln_g, ln_b, Woff, ppos, pxs);
    // 3. kv = x_sampled @ Wkv
    gemm_tf32<<<dim3(4,64), 256>>>(pxs, Wkv, pkv, 8192, 512, 256, nullptr);
    // 4. tensor-core attention with fused rpe bias
    attn_mma<<<dim3(16,8,8), 128>>>(pq, pkv, ppos, rpe, patt);
    // 5. out = att @ Wout + bout
    gemm_tf32<<<dim3(2,64), 256>>>(patt, Wout, outp, 8192, 256, 256, bout);
}

// round 16
// speedup vs baseline: 1.7776x; 1.7776x over previous
#include <cuda_runtime.h>
#include <math.h>

#define BB 8
#define NN 1024
#define DIMM 256
#define DGG 128
#define SCALE 0.17677669529663687f   // 32^-0.5
#define LOG2E 1.4426950408889634f
#define RPE_SZ (63*63)               // 3969

typedef unsigned long long ull;
typedef unsigned int uint;

__device__ __forceinline__ uint f2tf(float f) {
    uint r; asm("cvt.rna.tf32.f32 %0, %1;" : "=r"(r) : "f"(f)); return r;
}
// raw MUFU.EX2 — the whole point of the log2-domain softmax
__device__ __forceinline__ float ex2(float x) {
    float r; asm("ex2.approx.ftz.f32 %0, %1;" : "=f"(r) : "f"(x)); return r;
}

#define MMA_TF32(d, a, b) \
    asm("mma.sync.aligned.m16n8k8.row.col.f32.tf32.tf32.f32 " \
        "{%0,%1,%2,%3}, {%4,%5,%6,%7}, {%8,%9}, {%0,%1,%2,%3};" \
        : "+f"(d[0]), "+f"(d[1]), "+f"(d[2]), "+f"(d[3]) \
        : "r"(a[0]), "r"(a[1]), "r"(a[2]), "r"(a[3]), "r"(b[0]), "r"(b[1]))

// ---------------- scratch (static device globals; no allocs) ----------------
__device__ float g_q  [BB*NN*DIMM];      // q = x@Wq
__device__ float g_pos[BB*2*NN*2];       // sampling positions (y,x) per (bg,n)
__device__ float g_xs [BB*NN*DIMM];      // x_sampled
__device__ float g_kv [BB*NN*2*DIMM];    // kv = xs@Wkv
__device__ float g_att[BB*NN*DIMM];      // attention output (pre-Wout)

// ------ tf32 tensor-core GEMM, double-buffered: 128x128x16, 256 thr ---------
__global__ __launch_bounds__(256) void gemm_tf32(
    const float* __restrict__ A, const float* __restrict__ B,
    float* __restrict__ C, int M, int N, int K, const float* __restrict__ bias)
{
    __shared__ __align__(16) uint As[2][128][20];
    __shared__ __align__(16) uint Bs[2][16][136];
    const int tid  = threadIdx.x;
    const int lane = tid & 31, warp = tid >> 5;
    const int wm = (warp >> 1) * 32;
    const int wn = (warp & 1) * 64;
    const int gID = lane >> 2, tig = lane & 3;
    const int bm = blockIdx.y * 128, bn = blockIdx.x * 128;

    const int am  = tid >> 2, ak4 = (tid & 3) << 2;
    const int bkk = tid >> 5, bn4 = (tid & 31) << 2;

    float4 ra0, ra1, rb0, rb1;
    #define G_LD(k0) do { \
        ra0 = *(const float4*)&A[(size_t)(bm+am   )*K + (k0)+ak4]; \
        ra1 = *(const float4*)&A[(size_t)(bm+am+64)*K + (k0)+ak4]; \
        rb0 = *(const float4*)&B[(size_t)((k0)+bkk  )*N + bn+bn4]; \
        rb1 = *(const float4*)&B[(size_t)((k0)+bkk+8)*N + bn+bn4]; \
    } while(0)
    #define G_ST(bf) do { \
        uint4 t0 = {f2tf(ra0.x),f2tf(ra0.y),f2tf(ra0.z),f2tf(ra0.w)}; \
        uint4 t1 = {f2tf(ra1.x),f2tf(ra1.y),f2tf(ra1.z),f2tf(ra1.w)}; \
        uint4 t2 = {f2tf(rb0.x),f2tf(rb0.y),f2tf(rb0.z),f2tf(rb0.w)}; \
        uint4 t3 = {f2tf(rb1.x),f2tf(rb1.y),f2tf(rb1.z),f2tf(rb1.w)}; \
        *(uint4*)&As[bf][am   ][ak4] = t0; \
        *(uint4*)&As[bf][am+64][ak4] = t1; \
        *(uint4*)&Bs[bf][bkk  ][bn4] = t2; \
        *(uint4*)&Bs[bf][bkk+8][bn4] = t3; \
    } while(0)

    float c[2][8][4];
    #pragma unroll
    for (int rb=0;rb<2;rb++)
        #pragma unroll
        for (int nb=0;nb<8;nb++)
            #pragma unroll
            for (int r=0;r<4;r++) c[rb][nb][r]=0.f;

    G_LD(0); G_ST(0); __syncthreads();

    for (int k0 = 0; k0 < K; k0 += 16) {
        const int cur = (k0 >> 4) & 1;
        if (k0 + 16 < K) G_LD(k0 + 16);
        #pragma unroll
        for (int h8 = 0; h8 < 16; h8 += 8) {
            uint af[2][4];
            #pragma unroll
            for (int rb = 0; rb < 2; rb++) {
                int row = wm + rb*16;
                af[rb][0] = As[cur][row+gID  ][h8+tig  ];
                af[rb][1] = As[cur][row+gID+8][h8+tig  ];
                af[rb][2] = As[cur][row+gID  ][h8+tig+4];
                af[rb][3] = As[cur][row+gID+8][h8+tig+4];
            }
            uint bf[8][2];
            #pragma unroll
            for (int nb = 0; nb < 8; nb++) {
                int col = wn + nb*8 + gID;
                bf[nb][0] = Bs[cur][h8+tig  ][col];
                bf[nb][1] = Bs[cur][h8+tig+4][col];
            }
            #pragma unroll
            for (int rb = 0; rb < 2; rb++)
                #pragma unroll
                for (int nb = 0; nb < 8; nb++)
                    MMA_TF32(c[rb][nb], af[rb], bf[nb]);
        }
        if (k0 + 16 < K) { G_ST(cur^1); __syncthreads(); }
    }
    #pragma unroll
    for (int rb = 0; rb < 2; rb++) {
        int row0 = bm + wm + rb*16 + gID;
        #pragma unroll
        for (int nb = 0; nb < 8; nb++) {
            int col = bn + wn + nb*8 + tig*2;
            float b0 = 0.f, b1 = 0.f;
            if (bias) { float2 bv = *(const float2*)&bias[col]; b0 = bv.x; b1 = bv.y; }
            float2 o0 = {c[rb][nb][0] + b0, c[rb][nb][1] + b1};
            float2 o1 = {c[rb][nb][2] + b0, c[rb][nb][3] + b1};
            *(float2*)&C[(size_t)row0*N + col]     = o0;
            *(float2*)&C[(size_t)(row0+8)*N + col] = o1;
        }
    }
    #undef G_LD
    #undef G_ST
}

// -- conv 5x5 + LN + gelu + offset -> pos, FUSED with bilinear grid_sample ---
// grid 2048 (= 16 bg * 128 groups), 256 thr = 8 warps = 8 sites/block.
__global__ __launch_bounds__(256) void conv_sample_kernel(
    const float* __restrict__ q,
    const float* __restrict__ conv_w, const float* __restrict__ conv_b,
    const float* __restrict__ ln_g,   const float* __restrict__ ln_b,
    const float* __restrict__ Woff,   float* __restrict__ pos,
    float* __restrict__ xs)
{
    __shared__ float sw[25][128];    // transposed weights [tap][channel]
    const int tid = threadIdx.x;
    const int bg = blockIdx.x >> 7;
    const int b = bg >> 1, g = bg & 1;
    for (int idx = tid; idx < 25*128; idx += 256) {
        int cc = idx / 25, t = idx - cc*25;
        sw[t][cc] = conv_w[idx];
    }
    __syncthreads();

    const int warp = tid >> 5, lane = tid & 31;
    const int s = (blockIdx.x & 127)*8 + warp;   // site 0..1023
    const int y = s >> 5, x = s & 31;
    const int c4 = lane*4;

    float4 acc = *(const float4*)&conv_b[c4];
    const float* qbase = q + (size_t)b*NN*DIMM + g*DGG + c4;
    #pragma unroll
    for (int dy = 0; dy < 5; dy++) {
        int yy = y + dy - 2;
        if (yy < 0 || yy > 31) continue;
        #pragma unroll
        for (int dx = 0; dx < 5; dx++) {
            int xx = x + dx - 2;
            if (xx < 0 || xx > 31) continue;
            float4 qv = *(const float4*)&qbase[(size_t)(yy*32+xx)*DIMM];
            float4 wv = *(const float4*)&sw[dy*5+dx][c4];
            acc.x += qv.x*wv.x; acc.y += qv.y*wv.y;
            acc.z += qv.z*wv.z; acc.w += qv.w*wv.w;
        }
    }
    // LN over 128 channels
    float s1 = acc.x+acc.y+acc.z+acc.w;
    float s2 = acc.x*acc.x + acc.y*acc.y + acc.z*acc.z + acc.w*acc.w;
    #pragma unroll
    for (int o=16;o>0;o>>=1){ s1 += __shfl_xor_sync(0xffffffffu,s1,o);
                              s2 += __shfl_xor_sync(0xffffffffu,s2,o); }
    float mu  = s1 * (1.0f/128.0f);
    float var = s2 * (1.0f/128.0f) - mu*mu;
    float rstd = rsqrtf(var + 1e-5f);
    float4 lg4 = *(const float4*)&ln_g[c4];
    float4 lb4 = *(const float4*)&ln_b[c4];
    float v0 = (acc.x-mu)*rstd*lg4.x + lb4.x;
    float v1 = (acc.y-mu)*rstd*lg4.y + lb4.y;
    float v2 = (acc.z-mu)*rstd*lg4.z + lb4.z;
    float v3 = (acc.w-mu)*rstd*lg4.w + lb4.w;
    const float IS2 = 0.70710678118654752f;
    float ge0 = 0.5f*v0*(1.f+erff(v0*IS2));
    float ge1 = 0.5f*v1*(1.f+erff(v1*IS2));
    float ge2 = 0.5f*v2*(1.f+erff(v2*IS2));
    float ge3 = 0.5f*v3*(1.f+erff(v3*IS2));
    float4 wa = *(const float4*)&Woff[lane*8];
    float4 wb = *(const float4*)&Woff[lane*8+4];
    float o0 = ge0*wa.x + ge1*wa.z + ge2*wb.x + ge3*wb.z;
    float o1 = ge0*wa.y + ge1*wa.w + ge2*wb.y + ge3*wb.w;
    #pragma unroll
    for (int o=16;o>0;o>>=1){ o0 += __shfl_xor_sync(0xffffffffu,o0,o);
                              o1 += __shfl_xor_sync(0xffffffffu,o1,o); }
    float py = tanhf(o0)*0.0625f + ((2*y+1)*(1.0f/32.0f)-1.0f);
    float px = tanhf(o1)*0.0625f + ((2*x+1)*(1.0f/32.0f)-1.0f);
    if (lane == 0) {
        size_t idx = ((size_t)bg*NN + s)*2;
        pos[idx] = py; pos[idx+1] = px;
    }
    // ---- fused bilinear sample of this site's 4 channels ----
    const float pxs = (px + 1.f)*15.5f;
    const float pys = (py + 1.f)*15.5f;
    const float fx0 = floorf(pxs), fy0 = floorf(pys);
    float4 sacc = {0.f,0.f,0.f,0.f};
    #pragma unroll
    for (int dy=0; dy<2; dy++)
        #pragma unroll
        for (int dx=0; dx<2; dx++){
            float yi = fy0+dy, xi = fx0+dx;
            float wgt = (1.f - fabsf(pxs-xi))*(1.f - fabsf(pys-yi));
            bool valid = (yi>=0.f)&&(yi<32.f)&&(xi>=0.f)&&(xi<32.f);
            float w = valid ? wgt : 0.f;
            int yc = min(max((int)yi,0),31), xc = min(max((int)xi,0),31);
            float4 val = *(const float4*)&qbase[(size_t)(yc*32+xc)*DIMM];
            sacc.x += w*val.x; sacc.y += w*val.y; sacc.z += w*val.z; sacc.w += w*val.w;
        }
    *(float4*)&xs[((size_t)b*NN+s)*DIMM + g*DGG + c4] = sacc;
}

// ------------- tensor-core flash attention, double-buffered -----------------
// Block = (b, h, i-tile 64), 4 warps of 16 query rows; j-tile 32.
// log2-domain softmax with raw MUFU.EX2 (ex2.approx) — q and rpe pre-scaled
// by log2e. Weight guards dropped (pxr,pyr proven in [-0.01, 62.01]).
__global__ __launch_bounds__(128) void attn_mma(
    const float* __restrict__ q, const float* __restrict__ kv,
    const float* __restrict__ pos, const float* __restrict__ rpe,
    float* __restrict__ out)
{
    __shared__ __align__(16) uint sK[2][32][36];
    __shared__ __align__(16) uint sV[2][32][40];
    __shared__ __align__(16) uint sP[64][36];
    __shared__ float srpe[RPE_SZ];
    __shared__ float sPos[2][64];   // [0..32)=15.5*py, [32..64)=15.5*px

    const int it = blockIdx.x, h = blockIdx.y, b = blockIdx.z;
    const int bg = b*2 + (h>>2);
    const int tid = threadIdx.x;
    const int warp = tid>>5, lane = tid&31;
    const int gID = lane>>2, tig = lane&3;
    const int rb = warp*16;
    const int i0 = it*64 + rb + gID, i1 = i0 + 8;

    for (int t = tid; t < RPE_SZ; t += 128) srpe[t] = rpe[h*RPE_SZ + t] * LOG2E;

    const int lrow = tid >> 2, lq4 = (tid & 3) * 8;
    float4 rk0, rk1, rv0, rv1; float2 rpos;
    #define A_LD(jt) do { \
        const float* kp = &kv[((size_t)b*NN + (jt)*32 + lrow)*512 + h*32 + lq4]; \
        rk0 = *(const float4*)kp;       rk1 = *(const float4*)(kp+4); \
        rv0 = *(const float4*)(kp+256); rv1 = *(const float4*)(kp+260); \
        if (tid < 32) rpos = *(const float2*)&pos[((size_t)bg*NN + (jt)*32 + tid)*2]; \
    } while(0)
    #define A_ST(bf) do { \
        uint4 t0 = {f2tf(rk0.x),f2tf(rk0.y),f2tf(rk0.z),f2tf(rk0.w)}; \
        uint4 t1 = {f2tf(rk1.x),f2tf(rk1.y),f2tf(rk1.z),f2tf(rk1.w)}; \
        uint4 t2 = {f2tf(rv0.x),f2tf(rv0.y),f2tf(rv0.z),f2tf(rv0.w)}; \
        uint4 t3 = {f2tf(rv1.x),f2tf(rv1.y),f2tf(rv1.z),f2tf(rv1.w)}; \
        *(uint4*)&sK[bf][lrow][lq4  ] = t0; \
        *(uint4*)&sK[bf][lrow][lq4+4] = t1; \
        *(uint4*)&sV[bf][lrow][lq4  ] = t2; \
        *(uint4*)&sV[bf][lrow][lq4+4] = t3; \
        if (tid < 32) { sPos[bf][tid] = 15.5f*rpos.x; sPos[bf][32+tid] = 15.5f*rpos.y; } \
    } while(0)

    // Q fragments pre-scaled by SCALE*log2e
    uint qa[4][4];
    {
        const float QS = SCALE * LOG2E;
        const float* q0 = q + ((size_t)b*NN + i0)*DIMM + h*32;
        const float* q1 = q + ((size_t)b*NN + i1)*DIMM + h*32;
        #pragma unroll
        for (int k = 0; k < 4; k++) {
            qa[k][0] = f2tf(q0[k*8+tig  ]*QS);
            qa[k][1] = f2tf(q1[k*8+tig  ]*QS);
            qa[k][2] = f2tf(q0[k*8+tig+4]*QS);
            qa[k][3] = f2tf(q1[k*8+tig+4]*QS);
        }
    }
    const float cy  = 15.5f*((2*(i0>>5)+1)*(1.0f/32.0f)-1.0f) + 31.f;
    const float cx0 = 15.5f*((2*(i0&31)+1)*(1.0f/32.0f)-1.0f) + 31.f;
    const float cx1 = 15.5f*((2*(i1&31)+1)*(1.0f/32.0f)-1.0f) + 31.f;

    float dacc[4][4];
    #pragma unroll
    for (int nt=0;nt<4;nt++)
        #pragma unroll
        for (int r=0;r<4;r++) dacc[nt][r]=0.f;
    float l0 = 0.f, l1 = 0.f;

    A_LD(0); A_ST(0); __syncthreads();

    #pragma unroll 1
    for (int jt = 0; jt < 32; jt++) {
        const int cur = jt & 1;
        if (jt + 1 < 32) A_LD(jt + 1);

        // ---- S = Qs K^T (log2 domain) ----
        float c[4][4];
        #pragma unroll
        for (int nt=0;nt<4;nt++)
            #pragma unroll
            for (int r=0;r<4;r++) c[nt][r]=0.f;
        #pragma unroll
        for (int nt = 0; nt < 4; nt++) {
            #pragma unroll
            for (int k = 0; k < 4; k++) {
                uint bf[2] = { sK[cur][nt*8+gID][k*8+tig], sK[cur][nt*8+gID][k*8+tig+4] };
                MMA_TF32(c[nt], qa[k], bf);
            }
        }

        // ---- bias + ex2 -> tf32 P frags (y-part shared across both rows) ---
        uint pf[4][4];
        #pragma unroll
        for (int nt = 0; nt < 4; nt++) {
            #pragma unroll
            for (int cp = 0; cp < 2; cp++) {
                int jl = nt*8 + 2*tig + cp;
                float py = sPos[cur][jl], px = sPos[cur][32+jl];
                float pyr = cy - py;
                float fy = floorf(pyr); int y0 = (int)fy;
                float wy1 = pyr - fy, wy0 = 1.f - wy1;
                int yc0 = max(y0,0), yc1 = min(y0+1,62);
                const float* r0 = &srpe[yc0*63];
                const float* r1 = &srpe[yc1*63];
                {
                    float pxr = cx0 - px;
                    float fx = floorf(pxr); int x0 = (int)fx;
                    float wx1 = pxr - fx, wx0 = 1.f - wx1;
                    int xc0 = max(x0,0), xc1 = min(x0+1,62);
                    float bias = wy0*(wx0*r0[xc0] + wx1*r0[xc1])
                               + wy1*(wx0*r1[xc0] + wx1*r1[xc1]);
                    uint pu = f2tf(ex2(c[nt][cp] + bias));
                    l0 += __uint_as_float(pu);
                    pf[nt][cp] = pu;
                }
                {
                    float pxr = cx1 - px;
                    float fx = floorf(pxr); int x0 = (int)fx;
                    float wx1 = pxr - fx, wx0 = 1.f - wx1;
                    int xc0 = max(x0,0), xc1 = min(x0+1,62);
                    float bias = wy0*(wx0*r0[xc0] + wx1*r0[xc1])
                               + wy1*(wx0*r1[xc0] + wx1*r1[xc1]);
                    uint pu = f2tf(ex2(c[nt][cp+2] + bias));
                    l1 += __uint_as_float(pu);
                    pf[nt][cp+2] = pu;
                }
            }
        }

        // ---- P -> per-warp smem rows ----
        #pragma unroll
        for (int nt = 0; nt < 4; nt++) {
            *(uint2*)&sP[rb+gID  ][nt*8+2*tig] = make_uint2(pf[nt][0], pf[nt][1]);
            *(uint2*)&sP[rb+gID+8][nt*8+2*tig] = make_uint2(pf[nt][2], pf[nt][3]);
        }
        __syncwarp();

        // ---- O += P V ----
        #pragma unroll
        for (int k = 0; k < 4; k++) {
            uint a[4] = { sP[rb+gID  ][k*8+tig  ], sP[rb+gID+8][k*8+tig  ],
                          sP[rb+gID  ][k*8+tig+4], sP[rb+gID+8][k*8+tig+4] };
            #pragma unroll
            for (int nt = 0; nt < 4; nt++) {
                uint bf[2] = { sV[cur][k*8+tig][nt*8+gID], sV[cur][k*8+tig+4][nt*8+gID] };
                MMA_TF32(dacc[nt], a, bf);
            }
        }
        __syncwarp();

        if (jt + 1 < 32) { A_ST(cur^1); __syncthreads(); }
    }

    l0 += __shfl_xor_sync(0xffffffffu, l0, 1);
    l0 += __shfl_xor_sync(0xffffffffu, l0, 2);
    l1 += __shfl_xor_sync(0xffffffffu, l1, 1);
    l1 += __shfl_xor_sync(0xffffffffu, l1, 2);
    float inv0 = 1.f/l0, inv1 = 1.f/l1;
    float* o0 = out + ((size_t)b*NN + i0)*DIMM + h*32;
    float* o1 = out + ((size_t)b*NN + i1)*DIMM + h*32;
    #pragma unroll
    for (int nt = 0; nt < 4; nt++) {
        *(float2*)&o0[nt*8+2*tig] = make_float2(dacc[nt][0]*inv0, dacc[nt][1]*inv0);
        *(float2*)&o1[nt*8+2*tig] = make_float2(dacc[nt][2]*inv1, dacc[nt][3]*inv1);
    }
    #undef A_LD
    #undef A_ST
}

// ---------------------------------------------------------------------------
extern "C" void kernel_launch(void* const* d_in, const int* in_sizes, int n_in,
                              void* d_out, int out_size)
{
    const float* x      = (const float*)d_in[0];
    const float* Wq     = (const float*)d_in[1];
    const float* Wkv    = (const float*)d_in[2];
    const float* conv_w = (const float*)d_in[3];
    const float* conv_b = (const float*)d_in[4];
    const float* ln_g   = (const float*)d_in[5];
    const float* ln_b   = (const float*)d_in[6];
    const float* Woff   = (const float*)d_in[7];
    const float* rpe    = (const float*)d_in[8];
    const float* Wout   = (const float*)d_in[9];
    const float* bout   = (const float*)d_in[10];
    float* outp = (float*)d_out;

    float *pq, *ppos, *pxs, *pkv, *patt;
    cudaGetSymbolAddress((void**)&pq,   g_q);
    cudaGetSymbolAddress((void**)&ppos, g_pos);
    cudaGetSymbolAddress((void**)&pxs,  g_xs);
    cudaGetSymbolAddress((void**)&pkv,  g_kv);
    cudaGetSymbolAddress((void**)&patt, g_att);

    // 1. q = x @ Wq
    gemm_tf32<<<dim3(2,64), 256>>>(x, Wq, pq, 8192, 256, 256, nullptr);
    // 2. conv+LN+gelu+offset -> pos, fused with grid_sample -> xs
    conv_sample_kernel<<<2048, 256>>>(pq, conv_w, conv_b, ln_g, ln_b, Woff, ppos, pxs);
    // 3. kv = x_sampled @ Wkv
    gemm_tf32<<<dim3(4,64), 256>>>(pxs, Wkv, pkv, 8192, 512, 256, nullptr);
    // 4. tensor-core attention with fused rpe bias
    attn_mma<<<dim3(16,8,8), 128>>>(pq, pkv, ppos, rpe, patt);
    // 5. out = att @ Wout + bout
    gemm_tf32<<<dim3(2,64), 256>>>(patt, Wout, outp, 8192, 256, 256, bout);
}

// round 17
// speedup vs baseline: 1.9826x; 1.1153x over previous
#include <cuda_runtime.h>
#include <math.h>

#define BB 8
#define NN 1024
#define DIMM 256
#define DGG 128
#define SCALE 0.17677669529663687f   // 32^-0.5
#define LOG2E 1.4426950408889634f
#define RPE_SZ (63*63)               // 3969

typedef unsigned long long ull;
typedef unsigned int uint;

__device__ __forceinline__ uint f2tf(float f) {
    uint r; asm("cvt.rna.tf32.f32 %0, %1;" : "=r"(r) : "f"(f)); return r;
}
// raw MUFU.EX2 — log2-domain softmax
__device__ __forceinline__ float ex2(float x) {
    float r; asm("ex2.approx.ftz.f32 %0, %1;" : "=f"(r) : "f"(x)); return r;
}
// pack two floats to bf16x2 (hi -> upper 16, lo -> lower 16)
__device__ __forceinline__ uint pack_bf2(float hi, float lo) {
    uint u; asm("cvt.rn.bf16x2.f32 %0, %1, %2;" : "=r"(u) : "f"(hi), "f"(lo)); return u;
}

#define MMA_TF32(d, a, b) \
    asm("mma.sync.aligned.m16n8k8.row.col.f32.tf32.tf32.f32 " \
        "{%0,%1,%2,%3}, {%4,%5,%6,%7}, {%8,%9}, {%0,%1,%2,%3};" \
        : "+f"(d[0]), "+f"(d[1]), "+f"(d[2]), "+f"(d[3]) \
        : "r"(a[0]), "r"(a[1]), "r"(a[2]), "r"(a[3]), "r"(b[0]), "r"(b[1]))

// ---------------- scratch (static device globals; no allocs) ----------------
__device__ float g_q  [BB*NN*DIMM];      // q = x@Wq
__device__ float g_pos[BB*2*NN*2];       // sampling positions (y,x) per (bg,n)
__device__ float g_xs [BB*NN*DIMM];      // x_sampled
__device__ float g_kv [BB*NN*2*DIMM];    // kv = xs@Wkv
__device__ float g_att[BB*NN*DIMM];      // attention output (pre-Wout)

// ------ tf32 tensor-core GEMM, double-buffered: 128x128x16, 256 thr ---------
__global__ __launch_bounds__(256) void gemm_tf32(
    const float* __restrict__ A, const float* __restrict__ B,
    float* __restrict__ C, int M, int N, int K, const float* __restrict__ bias)
{
    __shared__ __align__(16) uint As[2][128][20];
    __shared__ __align__(16) uint Bs[2][16][136];
    const int tid  = threadIdx.x;
    const int lane = tid & 31, warp = tid >> 5;
    const int wm = (warp >> 1) * 32;
    const int wn = (warp & 1) * 64;
    const int gID = lane >> 2, tig = lane & 3;
    const int bm = blockIdx.y * 128, bn = blockIdx.x * 128;

    const int am  = tid >> 2, ak4 = (tid & 3) << 2;
    const int bkk = tid >> 5, bn4 = (tid & 31) << 2;

    float4 ra0, ra1, rb0, rb1;
    #define G_LD(k0) do { \
        ra0 = *(const float4*)&A[(size_t)(bm+am   )*K + (k0)+ak4]; \
        ra1 = *(const float4*)&A[(size_t)(bm+am+64)*K + (k0)+ak4]; \
        rb0 = *(const float4*)&B[(size_t)((k0)+bkk  )*N + bn+bn4]; \
        rb1 = *(const float4*)&B[(size_t)((k0)+bkk+8)*N + bn+bn4]; \
    } while(0)
    #define G_ST(bf) do { \
        uint4 t0 = {f2tf(ra0.x),f2tf(ra0.y),f2tf(ra0.z),f2tf(ra0.w)}; \
        uint4 t1 = {f2tf(ra1.x),f2tf(ra1.y),f2tf(ra1.z),f2tf(ra1.w)}; \
        uint4 t2 = {f2tf(rb0.x),f2tf(rb0.y),f2tf(rb0.z),f2tf(rb0.w)}; \
        uint4 t3 = {f2tf(rb1.x),f2tf(rb1.y),f2tf(rb1.z),f2tf(rb1.w)}; \
        *(uint4*)&As[bf][am   ][ak4] = t0; \
        *(uint4*)&As[bf][am+64][ak4] = t1; \
        *(uint4*)&Bs[bf][bkk  ][bn4] = t2; \
        *(uint4*)&Bs[bf][bkk+8][bn4] = t3; \
    } while(0)

    float c[2][8][4];
    #pragma unroll
    for (int rb=0;rb<2;rb++)
        #pragma unroll
        for (int nb=0;nb<8;nb++)
            #pragma unroll
            for (int r=0;r<4;r++) c[rb][nb][r]=0.f;

    G_LD(0); G_ST(0); __syncthreads();

    for (int k0 = 0; k0 < K; k0 += 16) {
        const int cur = (k0 >> 4) & 1;
        if (k0 + 16 < K) G_LD(k0 + 16);
        #pragma unroll
        for (int h8 = 0; h8 < 16; h8 += 8) {
            uint af[2][4];
            #pragma unroll
            for (int rb = 0; rb < 2; rb++) {
                int row = wm + rb*16;
                af[rb][0] = As[cur][row+gID  ][h8+tig  ];
                af[rb][1] = As[cur][row+gID+8][h8+tig  ];
                af[rb][2] = As[cur][row+gID  ][h8+tig+4];
                af[rb][3] = As[cur][row+gID+8][h8+tig+4];
            }
            uint bf[8][2];
            #pragma unroll
            for (int nb = 0; nb < 8; nb++) {
                int col = wn + nb*8 + gID;
                bf[nb][0] = Bs[cur][h8+tig  ][col];
                bf[nb][1] = Bs[cur][h8+tig+4][col];
            }
            #pragma unroll
            for (int rb = 0; rb < 2; rb++)
                #pragma unroll
                for (int nb = 0; nb < 8; nb++)
                    MMA_TF32(c[rb][nb], af[rb], bf[nb]);
        }
        if (k0 + 16 < K) { G_ST(cur^1); __syncthreads(); }
    }
    #pragma unroll
    for (int rb = 0; rb < 2; rb++) {
        int row0 = bm + wm + rb*16 + gID;
        #pragma unroll
        for (int nb = 0; nb < 8; nb++) {
            int col = bn + wn + nb*8 + tig*2;
            float b0 = 0.f, b1 = 0.f;
            if (bias) { float2 bv = *(const float2*)&bias[col]; b0 = bv.x; b1 = bv.y; }
            float2 o0 = {c[rb][nb][0] + b0, c[rb][nb][1] + b1};
            float2 o1 = {c[rb][nb][2] + b0, c[rb][nb][3] + b1};
            *(float2*)&C[(size_t)row0*N + col]     = o0;
            *(float2*)&C[(size_t)(row0+8)*N + col] = o1;
        }
    }
    #undef G_LD
    #undef G_ST
}

// -- conv 5x5 + LN + gelu + offset -> pos, FUSED with bilinear grid_sample ---
__global__ __launch_bounds__(256) void conv_sample_kernel(
    const float* __restrict__ q,
    const float* __restrict__ conv_w, const float* __restrict__ conv_b,
    const float* __restrict__ ln_g,   const float* __restrict__ ln_b,
    const float* __restrict__ Woff,   float* __restrict__ pos,
    float* __restrict__ xs)
{
    __shared__ float sw[25][128];
    const int tid = threadIdx.x;
    const int bg = blockIdx.x >> 7;
    const int b = bg >> 1, g = bg & 1;
    for (int idx = tid; idx < 25*128; idx += 256) {
        int cc = idx / 25, t = idx - cc*25;
        sw[t][cc] = conv_w[idx];
    }
    __syncthreads();

    const int warp = tid >> 5, lane = tid & 31;
    const int s = (blockIdx.x & 127)*8 + warp;
    const int y = s >> 5, x = s & 31;
    const int c4 = lane*4;

    float4 acc = *(const float4*)&conv_b[c4];
    const float* qbase = q + (size_t)b*NN*DIMM + g*DGG + c4;
    #pragma unroll
    for (int dy = 0; dy < 5; dy++) {
        int yy = y + dy - 2;
        if (yy < 0 || yy > 31) continue;
        #pragma unroll
        for (int dx = 0; dx < 5; dx++) {
            int xx = x + dx - 2;
            if (xx < 0 || xx > 31) continue;
            float4 qv = *(const float4*)&qbase[(size_t)(yy*32+xx)*DIMM];
            float4 wv = *(const float4*)&sw[dy*5+dx][c4];
            acc.x += qv.x*wv.x; acc.y += qv.y*wv.y;
            acc.z += qv.z*wv.z; acc.w += qv.w*wv.w;
        }
    }
    float s1 = acc.x+acc.y+acc.z+acc.w;
    float s2 = acc.x*acc.x + acc.y*acc.y + acc.z*acc.z + acc.w*acc.w;
    #pragma unroll
    for (int o=16;o>0;o>>=1){ s1 += __shfl_xor_sync(0xffffffffu,s1,o);
                              s2 += __shfl_xor_sync(0xffffffffu,s2,o); }
    float mu  = s1 * (1.0f/128.0f);
    float var = s2 * (1.0f/128.0f) - mu*mu;
    float rstd = rsqrtf(var + 1e-5f);
    float4 lg4 = *(const float4*)&ln_g[c4];
    float4 lb4 = *(const float4*)&ln_b[c4];
    float v0 = (acc.x-mu)*rstd*lg4.x + lb4.x;
    float v1 = (acc.y-mu)*rstd*lg4.y + lb4.y;
    float v2 = (acc.z-mu)*rstd*lg4.z + lb4.z;
    float v3 = (acc.w-mu)*rstd*lg4.w + lb4.w;
    const float IS2 = 0.70710678118654752f;
    float ge0 = 0.5f*v0*(1.f+erff(v0*IS2));
    float ge1 = 0.5f*v1*(1.f+erff(v1*IS2));
    float ge2 = 0.5f*v2*(1.f+erff(v2*IS2));
    float ge3 = 0.5f*v3*(1.f+erff(v3*IS2));
    float4 wa = *(const float4*)&Woff[lane*8];
    float4 wb = *(const float4*)&Woff[lane*8+4];
    float o0 = ge0*wa.x + ge1*wa.z + ge2*wb.x + ge3*wb.z;
    float o1 = ge0*wa.y + ge1*wa.w + ge2*wb.y + ge3*wb.w;
    #pragma unroll
    for (int o=16;o>0;o>>=1){ o0 += __shfl_xor_sync(0xffffffffu,o0,o);
                              o1 += __shfl_xor_sync(0xffffffffu,o1,o); }
    float py = tanhf(o0)*0.0625f + ((2*y+1)*(1.0f/32.0f)-1.0f);
    float px = tanhf(o1)*0.0625f + ((2*x+1)*(1.0f/32.0f)-1.0f);
    if (lane == 0) {
        size_t idx = ((size_t)bg*NN + s)*2;
        pos[idx] = py; pos[idx+1] = px;
    }
    const float pxs = (px + 1.f)*15.5f;
    const float pys = (py + 1.f)*15.5f;
    const float fx0 = floorf(pxs), fy0 = floorf(pys);
    float4 sacc = {0.f,0.f,0.f,0.f};
    #pragma unroll
    for (int dy=0; dy<2; dy++)
        #pragma unroll
        for (int dx=0; dx<2; dx++){
            float yi = fy0+dy, xi = fx0+dx;
            float wgt = (1.f - fabsf(pxs-xi))*(1.f - fabsf(pys-yi));
            bool valid = (yi>=0.f)&&(yi<32.f)&&(xi>=0.f)&&(xi<32.f);
            float w = valid ? wgt : 0.f;
            int yc = min(max((int)yi,0),31), xc = min(max((int)xi,0),31);
            float4 val = *(const float4*)&qbase[(size_t)(yc*32+xc)*DIMM];
            sacc.x += w*val.x; sacc.y += w*val.y; sacc.z += w*val.z; sacc.w += w*val.w;
        }
    *(float4*)&xs[((size_t)b*NN+s)*DIMM + g*DGG + c4] = sacc;
}

// ------------- tensor-core flash attention, double-buffered -----------------
// Block = (b, h, i-tile 64), 4 warps of 16 query rows; j-tile 32.
// log2-domain softmax via raw MUFU.EX2. Shared-pipe diet:
//  * P->PV via column-permutation (register relabel + sigma-permuted V rows):
//    no sP smem roundtrip (exact).
//  * K stored pair-packed (cols 0,4,1,5,2,6,3,7 per 8-group, pitch 40):
//    each QK B-frag is one LDS.64, conflict-free (exact).
//  * rpe in smem as bf16x2 (x, x+1) pairs: one LDS.32 per row-tap.
__global__ __launch_bounds__(128) void attn_mma(
    const float* __restrict__ q, const float* __restrict__ kv,
    const float* __restrict__ pos, const float* __restrict__ rpe,
    float* __restrict__ out)
{
    __shared__ __align__(16) uint sK[2][32][40];
    __shared__ __align__(16) uint sV[2][32][40];
    __shared__ uint srpe2[RPE_SZ];       // bf16x2: lo = rpe[y][x], hi = rpe[y][x+1]
    __shared__ float sPos[2][64];        // [0..32)=15.5*py, [32..64)=15.5*px

    const int it = blockIdx.x, h = blockIdx.y, b = blockIdx.z;
    const int bg = b*2 + (h>>2);
    const int tid = threadIdx.x;
    const int warp = tid>>5, lane = tid&31;
    const int gID = lane>>2, tig = lane&3;
    const int rb = warp*16;
    const int i0 = it*64 + rb + gID, i1 = i0 + 8;

    // build bf16x2 rpe pairs (scaled by log2e)
    for (int t = tid; t < RPE_SZ; t += 128) {
        int x = t % 63;
        float lo = rpe[h*RPE_SZ + t] * LOG2E;
        float hi = (x < 62) ? rpe[h*RPE_SZ + t + 1] * LOG2E : lo;
        srpe2[t] = pack_bf2(hi, lo);
    }

    const int lrow = tid >> 2, lq4 = (tid & 3) * 8;
    // sigma-permuted V row (within each 8-group): sigma(r) = (r>>1) | ((r&1)<<2)
    const int vrow = (lrow & 24) | ((lrow >> 1) & 3) | ((lrow & 1) << 2);
    float4 rk0, rk1, rv0, rv1; float2 rpos;
    #define A_LD(jt) do { \
        const float* kp = &kv[((size_t)b*NN + (jt)*32 + lrow)*512 + h*32 + lq4]; \
        rk0 = *(const float4*)kp;       rk1 = *(const float4*)(kp+4); \
        rv0 = *(const float4*)(kp+256); rv1 = *(const float4*)(kp+260); \
        if (tid < 32) rpos = *(const float2*)&pos[((size_t)bg*NN + (jt)*32 + tid)*2]; \
    } while(0)
    // K pair-packed: positions (2t,2t+1) <- cols (t, t+4); V straight cols, sigma rows
    #define A_ST(bf) do { \
        uint4 p0 = {f2tf(rk0.x),f2tf(rk1.x),f2tf(rk0.y),f2tf(rk1.y)}; \
        uint4 p1 = {f2tf(rk0.z),f2tf(rk1.z),f2tf(rk0.w),f2tf(rk1.w)}; \
        uint4 t2 = {f2tf(rv0.x),f2tf(rv0.y),f2tf(rv0.z),f2tf(rv0.w)}; \
        uint4 t3 = {f2tf(rv1.x),f2tf(rv1.y),f2tf(rv1.z),f2tf(rv1.w)}; \
        *(uint4*)&sK[bf][lrow][lq4  ] = p0; \
        *(uint4*)&sK[bf][lrow][lq4+4] = p1; \
        *(uint4*)&sV[bf][vrow][lq4  ] = t2; \
        *(uint4*)&sV[bf][vrow][lq4+4] = t3; \
        if (tid < 32) { sPos[bf][tid] = 15.5f*rpos.x; sPos[bf][32+tid] = 15.5f*rpos.y; } \
    } while(0)

    // Q fragments pre-scaled by SCALE*log2e
    uint qa[4][4];
    {
        const float QS = SCALE * LOG2E;
        const float* q0 = q + ((size_t)b*NN + i0)*DIMM + h*32;
        const float* q1 = q + ((size_t)b*NN + i1)*DIMM + h*32;
        #pragma unroll
        for (int k = 0; k < 4; k++) {
            qa[k][0] = f2tf(q0[k*8+tig  ]*QS);
            qa[k][1] = f2tf(q1[k*8+tig  ]*QS);
            qa[k][2] = f2tf(q0[k*8+tig+4]*QS);
            qa[k][3] = f2tf(q1[k*8+tig+4]*QS);
        }
    }
    const float cy  = 15.5f*((2*(i0>>5)+1)*(1.0f/32.0f)-1.0f) + 31.f;
    const float cx0 = 15.5f*((2*(i0&31)+1)*(1.0f/32.0f)-1.0f) + 31.f;
    const float cx1 = 15.5f*((2*(i1&31)+1)*(1.0f/32.0f)-1.0f) + 31.f;

    float dacc[4][4];
    #pragma unroll
    for (int nt=0;nt<4;nt++)
        #pragma unroll
        for (int r=0;r<4;r++) dacc[nt][r]=0.f;
    float l0 = 0.f, l1 = 0.f;

    A_LD(0); A_ST(0); __syncthreads();

    #pragma unroll 1
    for (int jt = 0; jt < 32; jt++) {
        const int cur = jt & 1;
        if (jt + 1 < 32) A_LD(jt + 1);

        // ---- S = Qs K^T (log2 domain); B-frag = one LDS.64 (pair-packed) ---
        float c[4][4];
        #pragma unroll
        for (int nt=0;nt<4;nt++)
            #pragma unroll
            for (int r=0;r<4;r++) c[nt][r]=0.f;
        #pragma unroll
        for (int nt = 0; nt < 4; nt++) {
            #pragma unroll
            for (int k = 0; k < 4; k++) {
                uint2 kp = *(const uint2*)&sK[cur][nt*8+gID][k*8 + 2*tig];
                uint bf[2] = { kp.x, kp.y };
                MMA_TF32(c[nt], qa[k], bf);
            }
        }

        // ---- bias + ex2 -> tf32 P frags ----
        uint pf[4][4];
        #pragma unroll
        for (int nt = 0; nt < 4; nt++) {
            #pragma unroll
            for (int cp = 0; cp < 2; cp++) {
                int jl = nt*8 + 2*tig + cp;
                float py = sPos[cur][jl], px = sPos[cur][32+jl];
                float pyr = cy - py;
                float fy = floorf(pyr); int y0 = (int)fy;
                float wy1 = pyr - fy, wy0 = 1.f - wy1;
                int yc0 = max(y0,0), yc1 = min(y0+1,62);
                const uint* r0 = &srpe2[yc0*63];
                const uint* r1 = &srpe2[yc1*63];
                {
                    float pxr = cx0 - px;
                    float fx = floorf(pxr); int x0 = (int)fx;
                    float wx1 = pxr - fx, wx0 = 1.f - wx1;
                    int xc0 = max(x0,0);
                    uint u0 = r0[xc0], u1 = r1[xc0];
                    float b00 = __uint_as_float(u0 << 16);
                    float b01 = __uint_as_float(u0 & 0xffff0000u);
                    float b10 = __uint_as_float(u1 << 16);
                    float b11 = __uint_as_float(u1 & 0xffff0000u);
                    float bias = wy0*(wx0*b00 + wx1*b01) + wy1*(wx0*b10 + wx1*b11);
                    uint pu = f2tf(ex2(c[nt][cp] + bias));
                    l0 += __uint_as_float(pu);
                    pf[nt][cp] = pu;
                }
                {
                    float pxr = cx1 - px;
                    float fx = floorf(pxr); int x0 = (int)fx;
                    float wx1 = pxr - fx, wx0 = 1.f - wx1;
                    int xc0 = max(x0,0);
                    uint u0 = r0[xc0], u1 = r1[xc0];
                    float b00 = __uint_as_float(u0 << 16);
                    float b01 = __uint_as_float(u0 & 0xffff0000u);
                    float b10 = __uint_as_float(u1 << 16);
                    float b11 = __uint_as_float(u1 & 0xffff0000u);
                    float bias = wy0*(wx0*b00 + wx1*b01) + wy1*(wx0*b10 + wx1*b11);
                    uint pu = f2tf(ex2(c[nt][cp+2] + bias));
                    l1 += __uint_as_float(pu);
                    pf[nt][cp+2] = pu;
                }
            }
        }

        // ---- O += P V  (P' column-permuted in registers; V rows sigma'd) ---
        #pragma unroll
        for (int k = 0; k < 4; k++) {
            uint a[4] = { pf[k][0], pf[k][2], pf[k][1], pf[k][3] };
            #pragma unroll
            for (int nt = 0; nt < 4; nt++) {
                uint bf[2] = { sV[cur][k*8+tig][nt*8+gID], sV[cur][k*8+tig+4][nt*8+gID] };
                MMA_TF32(dacc[nt], a, bf);
            }
        }

        if (jt + 1 < 32) { A_ST(cur^1); __syncthreads(); }
    }

    l0 += __shfl_xor_sync(0xffffffffu, l0, 1);
    l0 += __shfl_xor_sync(0xffffffffu, l0, 2);
    l1 += __shfl_xor_sync(0xffffffffu, l1, 1);
    l1 += __shfl_xor_sync(0xffffffffu, l1, 2);
    float inv0 = 1.f/l0, inv1 = 1.f/l1;
    float* o0 = out + ((size_t)b*NN + i0)*DIMM + h*32;
    float* o1 = out + ((size_t)b*NN + i1)*DIMM + h*32;
    #pragma unroll
    for (int nt = 0; nt < 4; nt++) {
        *(float2*)&o0[nt*8+2*tig] = make_float2(dacc[nt][0]*inv0, dacc[nt][1]*inv0);
        *(float2*)&o1[nt*8+2*tig] = make_float2(dacc[nt][2]*inv1, dacc[nt][3]*inv1);
    }
    #undef A_LD
    #undef A_ST
}

// ---------------------------------------------------------------------------
extern "C" void kernel_launch(void* const* d_in, const int* in_sizes, int n_in,
                              void* d_out, int out_size)
{
    const float* x      = (const float*)d_in[0];
    const float* Wq     = (const float*)d_in[1];
    const float* Wkv    = (const float*)d_in[2];
    const float* conv_w = (const float*)d_in[3];
    const float* conv_b = (const float*)d_in[4];
    const float* ln_g   = (const float*)d_in[5];
    const float* ln_b   = (const float*)d_in[6];
    const float* Woff   = (const float*)d_in[7];
    const float* rpe    = (const float*)d_in[8];
    const float* Wout   = (const float*)d_in[9];
    const float* bout   = (const float*)d_in[10];
    float* outp = (float*)d_out;

    float *pq, *ppos, *pxs, *pkv, *patt;
    cudaGetSymbolAddress((void**)&pq,   g_q);
    cudaGetSymbolAddress((void**)&ppos, g_pos);
    cudaGetSymbolAddress((void**)&pxs,  g_xs);
    cudaGetSymbolAddress((void**)&pkv,  g_kv);
    cudaGetSymbolAddress((void**)&patt, g_att);

    // 1. q = x @ Wq
    gemm_tf32<<<dim3(2,64), 256>>>(x, Wq, pq, 8192, 256, 256, nullptr);
    // 2. conv+LN+gelu+offset -> pos, fused with grid_sample -> xs
    conv_sample_kernel<<<2048, 256>>>(pq, conv_w, conv_b, ln_g, ln_b, Woff, ppos, pxs);
    // 3. kv = x_sampled @ Wkv
    gemm_tf32<<<dim3(4,64), 256>>>(pxs, Wkv, pkv, 8192, 512, 256, nullptr);
    // 4. tensor-core attention with fused rpe bias
    attn_mma<<<dim3(16,8,8), 128>>>(pq, pkv, ppos, rpe, patt);
    // 5. out = att @ Wout + bout
    gemm_tf32<<<dim3(2,64), 256>>>(patt, Wout, outp, 8192, 256, 256, bout);
}